// round 15
// baseline (speedup 1.0000x reference)
#include <cuda_runtime.h>
#include <cuda_fp16.h>
#include <math.h>

#define TOKENS 4096      // B*S = 2*2048
#define S_LEN  2048
#define HDIM   1024
#define NH     16

// Scratch (static device globals — no allocations allowed)
__device__ __align__(256) float  g_qkv[(size_t)TOKENS * 3 * HDIM]; // [token][3*1024]
__device__ __align__(256) __half g_xh [(size_t)TOKENS * HDIM];     // x in fp16
__device__ __align__(256) __half g_wqh[(size_t)3 * HDIM * HDIM];   // w_qkv fp16
__device__ __align__(256) __half g_woh[(size_t)HDIM * HDIM];       // w_o fp16
__device__ __align__(256) __half g_ath[(size_t)TOKENS * HDIM];     // att fp16
__device__ __align__(256) __half g_kh [(size_t)32 * S_LEN * 64];   // K fp16 frag-ordered
__device__ __align__(256) __half g_vph[(size_t)32 * 1024 * 64 * 2]; // V half2 pairs

// ---------------------------------------------------------------------------
// Helpers
// ---------------------------------------------------------------------------
__device__ __forceinline__ void hmma16(float* c, const unsigned* a, const unsigned* b) {
    asm("mma.sync.aligned.m16n8k16.row.col.f32.f16.f16.f32 "
        "{%0,%1,%2,%3}, {%4,%5,%6,%7}, {%8,%9}, {%0,%1,%2,%3};"
        : "+f"(c[0]), "+f"(c[1]), "+f"(c[2]), "+f"(c[3])
        : "r"(a[0]), "r"(a[1]), "r"(a[2]), "r"(a[3]), "r"(b[0]), "r"(b[1]));
}
// f16-accumulate variant: C/D are 2 regs of f16x2 ({col 2q, col 2q+1} packed)
__device__ __forceinline__ void hmma16h(unsigned* c, const unsigned* a, const unsigned* b) {
    asm("mma.sync.aligned.m16n8k16.row.col.f16.f16.f16.f16 "
        "{%0,%1}, {%2,%3,%4,%5}, {%6,%7}, {%0,%1};"
        : "+r"(c[0]), "+r"(c[1])
        : "r"(a[0]), "r"(a[1]), "r"(a[2]), "r"(a[3]), "r"(b[0]), "r"(b[1]));
}
__device__ __forceinline__ unsigned pkh2(float hi, float lo) {
    unsigned d; asm("cvt.rn.f16x2.f32 %0, %1, %2;" : "=r"(d) : "f"(hi), "f"(lo)); return d;
}
__device__ __forceinline__ unsigned hex2(unsigned x) {
    unsigned y; asm("ex2.approx.f16x2 %0, %1;" : "=r"(y) : "r"(x)); return y;
}
__device__ __forceinline__ unsigned hadd2(unsigned a, unsigned b) {
    unsigned d; asm("add.rn.f16x2 %0, %1, %2;" : "=r"(d) : "r"(a), "r"(b)); return d;
}
__device__ __forceinline__ void cpa16(void* s, const void* g) {
    unsigned sa = (unsigned)__cvta_generic_to_shared(s);
    asm volatile("cp.async.cg.shared.global [%0], [%1], 16;" :: "r"(sa), "l"(g));
}
__device__ __forceinline__ void cp_commit() { asm volatile("cp.async.commit_group;"); }
__device__ __forceinline__ void cp_wait0()  { asm volatile("cp.async.wait_group 0;"); }
__device__ __forceinline__ void cp_wait1()  { asm volatile("cp.async.wait_group 1;"); }
__device__ __forceinline__ void ldmx4(unsigned* r, unsigned addr) {
    asm volatile("ldmatrix.sync.aligned.m8n8.x4.shared.b16 {%0,%1,%2,%3}, [%4];"
        : "=r"(r[0]), "=r"(r[1]), "=r"(r[2]), "=r"(r[3]) : "r"(addr));
}

// ---------------------------------------------------------------------------
// fp32 -> fp16 convert (pre-pass)
// ---------------------------------------------------------------------------
__global__ void cvt_h(const float* __restrict__ s, __half* __restrict__ d, int n4) {
    int i = blockIdx.x * blockDim.x + threadIdx.x;
    if (i >= n4) return;
    float4 v = ((const float4*)s)[i];
    ((uint2*)d)[i] = make_uint2(pkh2(v.y, v.x), pkh2(v.w, v.z));
}

// ---------------------------------------------------------------------------
// fp16 GEMM (unchanged from round 14): 128x128 tile, 256 thr / 8 warps
// (4M x 2N), warp 32x64, 3-stage cp.async, coalesced + XOR swizzle.
// ---------------------------------------------------------------------------
#define GSM (3 * 32768)
__global__ void __launch_bounds__(256, 2) gemm_h_nt(
        const __half* __restrict__ A, const __half* __restrict__ B,
        float* __restrict__ C, int M, int N, int K) {
    extern __shared__ char smx[];   // [3][A 16KB | B 16KB]
    const int tid = threadIdx.x, lane = tid & 31;
    const int w   = tid >> 5, wm = w >> 1, wn = w & 1;
    const int g   = lane >> 2, q = lane & 3;

    const int lr = tid >> 3, lc = tid & 7;
    const __half* Ab = A + (size_t)(blockIdx.y * 128) * K + lc * 8;
    const __half* Bb = B + (size_t)(blockIdx.x * 128) * K + lc * 8;
    const unsigned sbase = (unsigned)__cvta_generic_to_shared(smx);

    const int lrow = ((lane >> 3) & 1) * 8 + (lane & 7);
    const unsigned rbA = sbase + (unsigned)(wm * 32 + lrow) * 128;
    const unsigned rbB = sbase + 16384u + (unsigned)(wn * 64 + lrow) * 128;
    const int gsel = lane >> 4;
    const int r7   = lane & 7;

    float acc[2][8][4] = {};
    const int nS = K >> 6;

    #pragma unroll
    for (int st = 0; st < 2; st++) {
        char* As = smx + st * 32768;
        char* Bs = As + 16384;
        const __half* a = Ab + st * 64;
        const __half* b = Bb + st * 64;
        #pragma unroll
        for (int i = 0; i < 4; i++) {
            const int r = lr + i * 32;
            const unsigned doff = (unsigned)(r * 128 + ((lc ^ (r & 7)) * 16));
            cpa16(As + doff, a + (size_t)r * K);
            cpa16(Bs + doff, b + (size_t)r * K);
        }
        cp_commit();
    }

    for (int s = 0; s < nS; s++) {
        cp_wait1();
        __syncthreads();

        if (s + 2 < nS) {
            char* As = smx + ((s + 2) % 3) * 32768;
            char* Bs = As + 16384;
            const __half* a = Ab + (s + 2) * 64;
            const __half* b = Bb + (s + 2) * 64;
            #pragma unroll
            for (int i = 0; i < 4; i++) {
                const int r = lr + i * 32;
                const unsigned doff = (unsigned)(r * 128 + ((lc ^ (r & 7)) * 16));
                cpa16(As + doff, a + (size_t)r * K);
                cpa16(Bs + doff, b + (size_t)r * K);
            }
        }
        cp_commit();

        const unsigned so = (unsigned)((s % 3) * 32768);
        #pragma unroll
        for (int kgi = 0; kgi < 4; kgi++) {
            const unsigned xo = (unsigned)((((kgi << 1) | gsel) ^ r7) * 16);
            unsigned af[2][4], bf[4][4];
            #pragma unroll
            for (int mb = 0; mb < 2; mb++) ldmx4(af[mb], rbA + so + mb * 2048 + xo);
            #pragma unroll
            for (int np = 0; np < 4; np++) ldmx4(bf[np], rbB + so + np * 2048 + xo);
            #pragma unroll
            for (int mb = 0; mb < 2; mb++)
                #pragma unroll
                for (int ni = 0; ni < 8; ni++) {
                    unsigned bb[2] = { bf[ni >> 1][ni & 1], bf[ni >> 1][(ni & 1) + 2] };
                    hmma16(acc[mb][ni], af[mb], bb);
                }
        }
        __syncthreads();
    }

    #pragma unroll
    for (int mb = 0; mb < 2; mb++) {
        const int row = blockIdx.y * 128 + wm * 32 + mb * 16 + g;
        #pragma unroll
        for (int ni = 0; ni < 8; ni++) {
            const int col = blockIdx.x * 128 + wn * 64 + ni * 8 + 2 * q;
            *(float2*)&C[(size_t)row * N + col]       = make_float2(acc[mb][ni][0], acc[mb][ni][1]);
            *(float2*)&C[(size_t)(row + 8) * N + col] = make_float2(acc[mb][ni][2], acc[mb][ni][3]);
        }
    }
}

// ---------------------------------------------------------------------------
// RoPE: q in place (fp32). k -> g_kh fp16 in m16n8k16 B-frag order:
//   pos(d) = ((d&7)>>1)*16 + (d>>4)*4 + ((d>>3)&1)*2 + (d&1)
// v -> g_vph fp16, paired (rows 2m,2m+1 interleaved as half2).
// ---------------------------------------------------------------------------
__global__ void rope_kernel(float* __restrict__ qkv, __half* __restrict__ kh,
                            __half* __restrict__ vph) {
    int idx = blockIdx.x * blockDim.x + threadIdx.x;
    if (idx >= TOKENS * NH * 32) return;
    int i     = idx & 31;
    int h     = (idx >> 5) & 15;
    int token = idx >> 9;
    int s     = token & (S_LEN - 1);
    int bh    = ((token >> 11) << 4) | h;

    double invf_d = exp(-((double)i / 32.0) * log(10000.0));
    float  invf   = (float)invf_d;
    float  ang    = (float)s * invf;
    float  c = cosf(ang), sn = sinf(ang);

    size_t base = (size_t)token * (3 * HDIM) + h * 64;
    float q1 = qkv[base + i], q2 = qkv[base + i + 32];
    qkv[base + i]      = q1 * c - q2 * sn;
    qkv[base + i + 32] = q2 * c + q1 * sn;

    float k1 = qkv[base + HDIM + i], k2 = qkv[base + HDIM + i + 32];
    float kr1 = k1 * c - k2 * sn, kr2 = k2 * c + k1 * sn;
    __half* kdst = kh + ((size_t)bh * S_LEN + s) * 64;
    int d0 = i, d1 = i + 32;
    #pragma unroll
    for (int e = 0; e < 2; e++) {
        int d = e ? d1 : d0;
        float v = e ? kr2 : kr1;
        int pos = ((d & 7) >> 1) * 16 + (d >> 4) * 4 + ((d >> 3) & 1) * 2 + (d & 1);
        kdst[pos] = __float2half_rn(v);
    }

    size_t vb = ((size_t)bh * 1024 + (s >> 1)) * 64;
    float v1 = qkv[base + 2 * HDIM + i], v2 = qkv[base + 2 * HDIM + i + 32];
    vph[(vb + d0) * 2 + (s & 1)] = __float2half_rn(v1);
    vph[(vb + d1) * 2 + (s & 1)] = __float2half_rn(v2);
}

// ---------------------------------------------------------------------------
// Flash attention: QK in f16-ACCUM mma (half rt if rt(f32)=2*rt(f16); S
// C-frags emerge pre-packed f16x2 -> ex2.f16x2 directly, no pack). Causal
// mask via add.rn.f16x2 with -inf. PV + row-sum (ones-MMA) stay f32-accum.
// Block = 128 q-rows of one (b,h); 4 warps x 32 rows. Writes att as fp16.
// ---------------------------------------------------------------------------
#define KH  72
#define VST 72
#define NINF_LO 0x0000FC00u
#define NINF_HI 0xFC000000u
__global__ void __launch_bounds__(128, 2) flash2(const float* __restrict__ qkv,
                                                 const __half* __restrict__ kh,
                                                 const __half2* __restrict__ vp,
                                                 __half* __restrict__ outh) {
    extern __shared__ float sm[];
    __half*  KsB = (__half*)sm;                         // [2][64][KH]
    __half2* VsB = (__half2*)(sm + (2 * 64 * KH) / 2);  // [2][32][VST]

    const int tid = threadIdx.x, lane = tid & 31, w = tid >> 5;
    const int g   = lane >> 2, q = lane & 3;
    const int qb  = gridDim.x - 1 - blockIdx.x;
    const int bh  = blockIdx.y;
    const int b   = bh >> 4, h = bh & 15;
    const int r0  = qb * 128 + w * 32;

    const float SC = 0.125f * 1.44269504088896340736f;
    unsigned qa[2][4][4];
    #pragma unroll
    for (int mi = 0; mi < 2; mi++) {
        const float* rl = qkv + (size_t)(b * S_LEN + r0 + mi * 16 + g) * 3072 + h * 64;
        const float* rh = rl + (size_t)8 * 3072;
        #pragma unroll
        for (int kg = 0; kg < 4; kg++) {
            float2 lo0 = *(const float2*)(rl + kg * 16 + 2 * q);
            float2 hi0 = *(const float2*)(rh + kg * 16 + 2 * q);
            float2 lo8 = *(const float2*)(rl + kg * 16 + 8 + 2 * q);
            float2 hi8 = *(const float2*)(rh + kg * 16 + 8 + 2 * q);
            qa[mi][kg][0] = pkh2(lo0.y * SC, lo0.x * SC);
            qa[mi][kg][1] = pkh2(hi0.y * SC, hi0.x * SC);
            qa[mi][kg][2] = pkh2(lo8.y * SC, lo8.x * SC);
            qa[mi][kg][3] = pkh2(hi8.y * SC, hi8.x * SC);
        }
    }

    float acc[2][8][4] = {};
    float accl[2][4] = {};
    const unsigned ONES[2] = { 0x3C003C00u, 0x3C003C00u };

    const __half*  Kpl = kh + (size_t)bh * S_LEN * 64;
    const __half2* Vpl = vp + (size_t)bh * 1024 * 64;

    const int kR = tid >> 3, kC = (tid & 7) * 8;
    const int vR = tid >> 2, vC = (tid & 3) * 16;
    const int jmax = 2 * qb + 1;

    {
        #pragma unroll
        for (int i = 0; i < 4; i++)
            cpa16(KsB + (kR + i * 16) * KH + kC, Kpl + (size_t)(kR + i * 16) * 64 + kC);
        #pragma unroll
        for (int i = 0; i < 4; i++)
            cpa16(VsB + vR * VST + vC + 4 * i, Vpl + (size_t)vR * 64 + vC + 4 * i);
    }
    cp_commit();

    for (int jb = 0; jb <= jmax; jb++) {
        cp_wait0();
        __syncthreads();

        if (jb < jmax) {
            const int nb = (jb + 1) & 1;
            const __half*  ks = Kpl + (size_t)((jb + 1) * 64) * 64;
            const __half2* vs = Vpl + (size_t)((jb + 1) * 32 + vR) * 64 + vC;
            #pragma unroll
            for (int i = 0; i < 4; i++)
                cpa16(KsB + (nb * 64 + kR + i * 16) * KH + kC, ks + (size_t)(kR + i * 16) * 64 + kC);
            #pragma unroll
            for (int i = 0; i < 4; i++)
                cpa16(VsB + (nb * 32 + vR) * VST + vC + 4 * i, vs + 4 * i);
            cp_commit();
        }

        if (r0 + 31 >= jb * 64) {
            const __half*  K = KsB + (jb & 1) * 64 * KH;
            const __half2* V = VsB + (jb & 1) * 32 * VST;
            const bool diag = (jb * 64 + 63 > r0);

            // ---- S = Q @ K^T in f16 accum; mask; p = 2^s (packed MUFU)
            unsigned pp[2][8][2];
            #pragma unroll
            for (int n = 0; n < 8; n++) {
                unsigned c0[2] = { 0u, 0u }, c1[2] = { 0u, 0u };
                const uint4* krow = (const uint4*)(K + (n * 8 + g) * KH + q * 16);
                uint4 k0 = krow[0];
                uint4 k1 = krow[1];
                unsigned b0[2] = { k0.x, k0.y }, b1[2] = { k0.z, k0.w };
                unsigned b2[2] = { k1.x, k1.y }, b3[2] = { k1.z, k1.w };
                hmma16h(c0, qa[0][0], b0); hmma16h(c0, qa[0][1], b1);
                hmma16h(c0, qa[0][2], b2); hmma16h(c0, qa[0][3], b3);
                hmma16h(c1, qa[1][0], b0); hmma16h(c1, qa[1][1], b1);
                hmma16h(c1, qa[1][2], b2); hmma16h(c1, qa[1][3], b3);

                if (diag) {
                    const int cc = jb * 64 + n * 8 + 2 * q;
                    const int rL = r0 + g, rH = rL + 8;
                    unsigned m;
                    m = (cc > rL ? NINF_LO : 0u) | (cc + 1 > rL ? NINF_HI : 0u);
                    if (m) c0[0] = hadd2(c0[0], m);
                    m = (cc > rH ? NINF_LO : 0u) | (cc + 1 > rH ? NINF_HI : 0u);
                    if (m) c0[1] = hadd2(c0[1], m);
                    m = (cc > rL + 16 ? NINF_LO : 0u) | (cc + 1 > rL + 16 ? NINF_HI : 0u);
                    if (m) c1[0] = hadd2(c1[0], m);
                    m = (cc > rH + 16 ? NINF_LO : 0u) | (cc + 1 > rH + 16 ? NINF_HI : 0u);
                    if (m) c1[1] = hadd2(c1[1], m);
                }

                pp[0][n][0] = hex2(c0[0]); pp[0][n][1] = hex2(c0[1]);
                pp[1][n][0] = hex2(c1[0]); pp[1][n][1] = hex2(c1[1]);
            }

            // ---- acc += P @ V ; l += P @ 1  (pp ARE the A-frags)
            #pragma unroll
            for (int t = 0; t < 4; t++) {
                unsigned pa[2][4];
                #pragma unroll
                for (int mi = 0; mi < 2; mi++) {
                    pa[mi][0] = pp[mi][2 * t][0];
                    pa[mi][1] = pp[mi][2 * t][1];
                    pa[mi][2] = pp[mi][2 * t + 1][0];
                    pa[mi][3] = pp[mi][2 * t + 1][1];
                }
                hmma16(accl[0], pa[0], ONES);
                hmma16(accl[1], pa[1], ONES);
                #pragma unroll
                for (int n = 0; n < 8; n++) {
                    unsigned vb[2] = {
                        *(const unsigned*)&V[(t * 8 + q) * VST + n * 8 + g],
                        *(const unsigned*)&V[(t * 8 + q + 4) * VST + n * 8 + g] };
                    hmma16(acc[0][n], pa[0], vb);
                    hmma16(acc[1][n], pa[1], vb);
                }
            }
        }
    }

    #pragma unroll
    for (int mi = 0; mi < 2; mi++) {
        const float inv0 = 1.f / accl[mi][0], inv1 = 1.f / accl[mi][2];
        const size_t tokL = (size_t)(b * S_LEN + r0 + mi * 16 + g);
        const size_t tokH = tokL + 8;
        #pragma unroll
        for (int n = 0; n < 8; n++) {
            const int c = h * 64 + n * 8 + 2 * q;
            *(unsigned*)&outh[tokL * HDIM + c] = pkh2(acc[mi][n][1] * inv0, acc[mi][n][0] * inv0);
            *(unsigned*)&outh[tokH * HDIM + c] = pkh2(acc[mi][n][3] * inv1, acc[mi][n][2] * inv1);
        }
    }
}

// ---------------------------------------------------------------------------
// Launch
// ---------------------------------------------------------------------------
extern "C" void kernel_launch(void* const* d_in, const int* in_sizes, int n_in,
                              void* d_out, int out_size) {
    const float* x     = (const float*)d_in[0];
    const float* w_qkv = (const float*)d_in[1];
    const float* w_o   = (const float*)d_in[2];
    float* out = (float*)d_out;

    float* qkv; __half *xh, *wqh, *woh, *ath, *khp, *vph;
    cudaGetSymbolAddress((void**)&qkv, g_qkv);
    cudaGetSymbolAddress((void**)&xh,  g_xh);
    cudaGetSymbolAddress((void**)&wqh, g_wqh);
    cudaGetSymbolAddress((void**)&woh, g_woh);
    cudaGetSymbolAddress((void**)&ath, g_ath);
    cudaGetSymbolAddress((void**)&khp, g_kh);
    cudaGetSymbolAddress((void**)&vph, g_vph);

    // 0) fp16 conversions
    cvt_h<<<(TOKENS * HDIM / 4 + 255) / 256, 256>>>(x, xh, TOKENS * HDIM / 4);
    cvt_h<<<(3 * HDIM * HDIM / 4 + 255) / 256, 256>>>(w_qkv, wqh, 3 * HDIM * HDIM / 4);
    cvt_h<<<(HDIM * HDIM / 4 + 255) / 256, 256>>>(w_o, woh, HDIM * HDIM / 4);

    // 1) QKV projection
    cudaFuncSetAttribute(gemm_h_nt, cudaFuncAttributeMaxDynamicSharedMemorySize, GSM);
    gemm_h_nt<<<dim3(3 * HDIM / 128, TOKENS / 128), 256, GSM>>>(xh, wqh, qkv, TOKENS, 3 * HDIM, HDIM);

    // 2) RoPE + K fp16 frag-reorder + V fp16 pairing
    rope_kernel<<<(TOKENS * NH * 32) / 256, 256>>>(qkv, khp, vph);

    // 3) Causal flash attention (f16-accum QK) -> att fp16
    const int flash_smem = 2 * 64 * KH * 2 + 2 * 32 * VST * 4;  // 36864 B
    cudaFuncSetAttribute(flash2, cudaFuncAttributeMaxDynamicSharedMemorySize, flash_smem);
    flash2<<<dim3(S_LEN / 128, 2 * NH), 128, flash_smem>>>(qkv, khp, (const __half2*)vph, ath);

    // 4) Output projection
    gemm_h_nt<<<dim3(HDIM / 128, TOKENS / 128), 256, GSM>>>(ath, woh, out, TOKENS, HDIM, HDIM);
}

// round 16
// speedup vs baseline: 1.0126x; 1.0126x over previous
#include <cuda_runtime.h>
#include <cuda_fp16.h>
#include <math.h>

#define TOKENS 4096      // B*S = 2*2048
#define S_LEN  2048
#define HDIM   1024
#define NH     16

// Scratch (static device globals — no allocations allowed)
__device__ __align__(256) float  g_qkv[(size_t)TOKENS * 3 * HDIM]; // [token][3*1024]
__device__ __align__(256) __half g_xh [(size_t)TOKENS * HDIM];     // x in fp16
__device__ __align__(256) __half g_wqh[(size_t)3 * HDIM * HDIM];   // w_qkv fp16
__device__ __align__(256) __half g_woh[(size_t)HDIM * HDIM];       // w_o fp16
__device__ __align__(256) __half g_ath[(size_t)TOKENS * HDIM];     // att fp16
__device__ __align__(256) __half g_kh [(size_t)32 * S_LEN * 64];   // K fp16 frag-ordered
__device__ __align__(256) __half g_vph[(size_t)32 * 1024 * 64 * 2]; // V half2 pairs

// ---------------------------------------------------------------------------
// Helpers
// ---------------------------------------------------------------------------
__device__ __forceinline__ void hmma16(float* c, const unsigned* a, const unsigned* b) {
    asm("mma.sync.aligned.m16n8k16.row.col.f32.f16.f16.f32 "
        "{%0,%1,%2,%3}, {%4,%5,%6,%7}, {%8,%9}, {%0,%1,%2,%3};"
        : "+f"(c[0]), "+f"(c[1]), "+f"(c[2]), "+f"(c[3])
        : "r"(a[0]), "r"(a[1]), "r"(a[2]), "r"(a[3]), "r"(b[0]), "r"(b[1]));
}
// f16-accumulate variant: C/D are 2 regs of f16x2 ({col 2q, col 2q+1} packed)
__device__ __forceinline__ void hmma16h(unsigned* c, const unsigned* a, const unsigned* b) {
    asm("mma.sync.aligned.m16n8k16.row.col.f16.f16.f16.f16 "
        "{%0,%1}, {%2,%3,%4,%5}, {%6,%7}, {%0,%1};"
        : "+r"(c[0]), "+r"(c[1])
        : "r"(a[0]), "r"(a[1]), "r"(a[2]), "r"(a[3]), "r"(b[0]), "r"(b[1]));
}
__device__ __forceinline__ unsigned pkh2(float hi, float lo) {
    unsigned d; asm("cvt.rn.f16x2.f32 %0, %1, %2;" : "=r"(d) : "f"(hi), "f"(lo)); return d;
}
__device__ __forceinline__ unsigned hex2(unsigned x) {
    unsigned y; asm("ex2.approx.f16x2 %0, %1;" : "=r"(y) : "r"(x)); return y;
}
__device__ __forceinline__ unsigned hadd2(unsigned a, unsigned b) {
    unsigned d; asm("add.rn.f16x2 %0, %1, %2;" : "=r"(d) : "r"(a), "r"(b)); return d;
}
__device__ __forceinline__ void cpa16(void* s, const void* g) {
    unsigned sa = (unsigned)__cvta_generic_to_shared(s);
    asm volatile("cp.async.cg.shared.global [%0], [%1], 16;" :: "r"(sa), "l"(g));
}
__device__ __forceinline__ void cp_commit() { asm volatile("cp.async.commit_group;"); }
__device__ __forceinline__ void cp_wait0()  { asm volatile("cp.async.wait_group 0;"); }
__device__ __forceinline__ void cp_wait1()  { asm volatile("cp.async.wait_group 1;"); }
__device__ __forceinline__ void ldmx4(unsigned* r, unsigned addr) {
    asm volatile("ldmatrix.sync.aligned.m8n8.x4.shared.b16 {%0,%1,%2,%3}, [%4];"
        : "=r"(r[0]), "=r"(r[1]), "=r"(r[2]), "=r"(r[3]) : "r"(addr));
}

// ---------------------------------------------------------------------------
// fp32 -> fp16 convert (pre-pass)
// ---------------------------------------------------------------------------
__global__ void cvt_h(const float* __restrict__ s, __half* __restrict__ d, int n4) {
    int i = blockIdx.x * blockDim.x + threadIdx.x;
    if (i >= n4) return;
    float4 v = ((const float4*)s)[i];
    ((uint2*)d)[i] = make_uint2(pkh2(v.y, v.x), pkh2(v.w, v.z));
}

// ---------------------------------------------------------------------------
// fp16 GEMM (at the mma.sync issue floor ~268 TF/s — final shape):
// 128x128 tile, 256 thr / 8 warps (4M x 2N), warp 32x64, 3-stage cp.async,
// coalesced loads + XOR swizzle for conflict-free ldmatrix.x4.
// ---------------------------------------------------------------------------
#define GSM (3 * 32768)
__global__ void __launch_bounds__(256, 2) gemm_h_nt(
        const __half* __restrict__ A, const __half* __restrict__ B,
        float* __restrict__ C, int M, int N, int K) {
    extern __shared__ char smx[];   // [3][A 16KB | B 16KB]
    const int tid = threadIdx.x, lane = tid & 31;
    const int w   = tid >> 5, wm = w >> 1, wn = w & 1;
    const int g   = lane >> 2, q = lane & 3;

    const int lr = tid >> 3, lc = tid & 7;
    const __half* Ab = A + (size_t)(blockIdx.y * 128) * K + lc * 8;
    const __half* Bb = B + (size_t)(blockIdx.x * 128) * K + lc * 8;
    const unsigned sbase = (unsigned)__cvta_generic_to_shared(smx);

    const int lrow = ((lane >> 3) & 1) * 8 + (lane & 7);
    const unsigned rbA = sbase + (unsigned)(wm * 32 + lrow) * 128;
    const unsigned rbB = sbase + 16384u + (unsigned)(wn * 64 + lrow) * 128;
    const int gsel = lane >> 4;
    const int r7   = lane & 7;

    float acc[2][8][4] = {};
    const int nS = K >> 6;

    #pragma unroll
    for (int st = 0; st < 2; st++) {
        char* As = smx + st * 32768;
        char* Bs = As + 16384;
        const __half* a = Ab + st * 64;
        const __half* b = Bb + st * 64;
        #pragma unroll
        for (int i = 0; i < 4; i++) {
            const int r = lr + i * 32;
            const unsigned doff = (unsigned)(r * 128 + ((lc ^ (r & 7)) * 16));
            cpa16(As + doff, a + (size_t)r * K);
            cpa16(Bs + doff, b + (size_t)r * K);
        }
        cp_commit();
    }

    for (int s = 0; s < nS; s++) {
        cp_wait1();
        __syncthreads();

        if (s + 2 < nS) {
            char* As = smx + ((s + 2) % 3) * 32768;
            char* Bs = As + 16384;
            const __half* a = Ab + (s + 2) * 64;
            const __half* b = Bb + (s + 2) * 64;
            #pragma unroll
            for (int i = 0; i < 4; i++) {
                const int r = lr + i * 32;
                const unsigned doff = (unsigned)(r * 128 + ((lc ^ (r & 7)) * 16));
                cpa16(As + doff, a + (size_t)r * K);
                cpa16(Bs + doff, b + (size_t)r * K);
            }
        }
        cp_commit();

        const unsigned so = (unsigned)((s % 3) * 32768);
        #pragma unroll
        for (int kgi = 0; kgi < 4; kgi++) {
            const unsigned xo = (unsigned)((((kgi << 1) | gsel) ^ r7) * 16);
            unsigned af[2][4], bf[4][4];
            #pragma unroll
            for (int mb = 0; mb < 2; mb++) ldmx4(af[mb], rbA + so + mb * 2048 + xo);
            #pragma unroll
            for (int np = 0; np < 4; np++) ldmx4(bf[np], rbB + so + np * 2048 + xo);
            #pragma unroll
            for (int mb = 0; mb < 2; mb++)
                #pragma unroll
                for (int ni = 0; ni < 8; ni++) {
                    unsigned bb[2] = { bf[ni >> 1][ni & 1], bf[ni >> 1][(ni & 1) + 2] };
                    hmma16(acc[mb][ni], af[mb], bb);
                }
        }
        __syncthreads();
    }

    #pragma unroll
    for (int mb = 0; mb < 2; mb++) {
        const int row = blockIdx.y * 128 + wm * 32 + mb * 16 + g;
        #pragma unroll
        for (int ni = 0; ni < 8; ni++) {
            const int col = blockIdx.x * 128 + wn * 64 + ni * 8 + 2 * q;
            *(float2*)&C[(size_t)row * N + col]       = make_float2(acc[mb][ni][0], acc[mb][ni][1]);
            *(float2*)&C[(size_t)(row + 8) * N + col] = make_float2(acc[mb][ni][2], acc[mb][ni][3]);
        }
    }
}

// ---------------------------------------------------------------------------
// RoPE: q in place (fp32). k -> g_kh fp16 in m16n8k16 B-frag order:
//   pos(d) = ((d&7)>>1)*16 + (d>>4)*4 + ((d>>3)&1)*2 + (d&1)
// v -> g_vph fp16, paired (rows 2m,2m+1 interleaved as half2).
// ---------------------------------------------------------------------------
__global__ void rope_kernel(float* __restrict__ qkv, __half* __restrict__ kh,
                            __half* __restrict__ vph) {
    int idx = blockIdx.x * blockDim.x + threadIdx.x;
    if (idx >= TOKENS * NH * 32) return;
    int i     = idx & 31;
    int h     = (idx >> 5) & 15;
    int token = idx >> 9;
    int s     = token & (S_LEN - 1);
    int bh    = ((token >> 11) << 4) | h;

    double invf_d = exp(-((double)i / 32.0) * log(10000.0));
    float  invf   = (float)invf_d;
    float  ang    = (float)s * invf;
    float  c = cosf(ang), sn = sinf(ang);

    size_t base = (size_t)token * (3 * HDIM) + h * 64;
    float q1 = qkv[base + i], q2 = qkv[base + i + 32];
    qkv[base + i]      = q1 * c - q2 * sn;
    qkv[base + i + 32] = q2 * c + q1 * sn;

    float k1 = qkv[base + HDIM + i], k2 = qkv[base + HDIM + i + 32];
    float kr1 = k1 * c - k2 * sn, kr2 = k2 * c + k1 * sn;
    __half* kdst = kh + ((size_t)bh * S_LEN + s) * 64;
    int d0 = i, d1 = i + 32;
    #pragma unroll
    for (int e = 0; e < 2; e++) {
        int d = e ? d1 : d0;
        float v = e ? kr2 : kr1;
        int pos = ((d & 7) >> 1) * 16 + (d >> 4) * 4 + ((d >> 3) & 1) * 2 + (d & 1);
        kdst[pos] = __float2half_rn(v);
    }

    size_t vb = ((size_t)bh * 1024 + (s >> 1)) * 64;
    float v1 = qkv[base + 2 * HDIM + i], v2 = qkv[base + 2 * HDIM + i + 32];
    vph[(vb + d0) * 2 + (s & 1)] = __float2half_rn(v1);
    vph[(vb + d1) * 2 + (s & 1)] = __float2half_rn(v2);
}

// ---------------------------------------------------------------------------
// Flash attention: f16-accum QK (S emerges pre-packed f16x2 -> ex2 direct),
// causal mask via add.rn.f16x2(-inf), PV + ones-MMA row-sum in f32.
// NOW at 3 CTAs/SM (lean register body fits 170 without spills).
// Block = 128 q-rows of one (b,h); 4 warps x 32 rows. Writes att as fp16.
// ---------------------------------------------------------------------------
#define KH  72
#define VST 72
#define NINF_LO 0x0000FC00u
#define NINF_HI 0xFC000000u
__global__ void __launch_bounds__(128, 3) flash2(const float* __restrict__ qkv,
                                                 const __half* __restrict__ kh,
                                                 const __half2* __restrict__ vp,
                                                 __half* __restrict__ outh) {
    extern __shared__ float sm[];
    __half*  KsB = (__half*)sm;                         // [2][64][KH]
    __half2* VsB = (__half2*)(sm + (2 * 64 * KH) / 2);  // [2][32][VST]

    const int tid = threadIdx.x, lane = tid & 31, w = tid >> 5;
    const int g   = lane >> 2, q = lane & 3;
    const int qb  = gridDim.x - 1 - blockIdx.x;
    const int bh  = blockIdx.y;
    const int b   = bh >> 4, h = bh & 15;
    const int r0  = qb * 128 + w * 32;

    const float SC = 0.125f * 1.44269504088896340736f;
    unsigned qa[2][4][4];
    #pragma unroll
    for (int mi = 0; mi < 2; mi++) {
        const float* rl = qkv + (size_t)(b * S_LEN + r0 + mi * 16 + g) * 3072 + h * 64;
        const float* rh = rl + (size_t)8 * 3072;
        #pragma unroll
        for (int kg = 0; kg < 4; kg++) {
            float2 lo0 = *(const float2*)(rl + kg * 16 + 2 * q);
            float2 hi0 = *(const float2*)(rh + kg * 16 + 2 * q);
            float2 lo8 = *(const float2*)(rl + kg * 16 + 8 + 2 * q);
            float2 hi8 = *(const float2*)(rh + kg * 16 + 8 + 2 * q);
            qa[mi][kg][0] = pkh2(lo0.y * SC, lo0.x * SC);
            qa[mi][kg][1] = pkh2(hi0.y * SC, hi0.x * SC);
            qa[mi][kg][2] = pkh2(lo8.y * SC, lo8.x * SC);
            qa[mi][kg][3] = pkh2(hi8.y * SC, hi8.x * SC);
        }
    }

    float acc[2][8][4] = {};
    float accl[2][4] = {};
    const unsigned ONES[2] = { 0x3C003C00u, 0x3C003C00u };

    const __half*  Kpl = kh + (size_t)bh * S_LEN * 64;
    const __half2* Vpl = vp + (size_t)bh * 1024 * 64;

    const int kR = tid >> 3, kC = (tid & 7) * 8;
    const int vR = tid >> 2, vC = (tid & 3) * 16;
    const int jmax = 2 * qb + 1;

    {
        #pragma unroll
        for (int i = 0; i < 4; i++)
            cpa16(KsB + (kR + i * 16) * KH + kC, Kpl + (size_t)(kR + i * 16) * 64 + kC);
        #pragma unroll
        for (int i = 0; i < 4; i++)
            cpa16(VsB + vR * VST + vC + 4 * i, Vpl + (size_t)vR * 64 + vC + 4 * i);
    }
    cp_commit();

    for (int jb = 0; jb <= jmax; jb++) {
        cp_wait0();
        __syncthreads();

        if (jb < jmax) {
            const int nb = (jb + 1) & 1;
            const __half*  ks = Kpl + (size_t)((jb + 1) * 64) * 64;
            const __half2* vs = Vpl + (size_t)((jb + 1) * 32 + vR) * 64 + vC;
            #pragma unroll
            for (int i = 0; i < 4; i++)
                cpa16(KsB + (nb * 64 + kR + i * 16) * KH + kC, ks + (size_t)(kR + i * 16) * 64 + kC);
            #pragma unroll
            for (int i = 0; i < 4; i++)
                cpa16(VsB + (nb * 32 + vR) * VST + vC + 4 * i, vs + 4 * i);
            cp_commit();
        }

        if (r0 + 31 >= jb * 64) {
            const __half*  K = KsB + (jb & 1) * 64 * KH;
            const __half2* V = VsB + (jb & 1) * 32 * VST;
            const bool diag = (jb * 64 + 63 > r0);

            // ---- S = Q @ K^T in f16 accum; mask; p = 2^s (packed MUFU)
            unsigned pp[2][8][2];
            #pragma unroll
            for (int n = 0; n < 8; n++) {
                unsigned c0[2] = { 0u, 0u }, c1[2] = { 0u, 0u };
                const uint4* krow = (const uint4*)(K + (n * 8 + g) * KH + q * 16);
                uint4 k0 = krow[0];
                uint4 k1 = krow[1];
                unsigned b0[2] = { k0.x, k0.y }, b1[2] = { k0.z, k0.w };
                unsigned b2[2] = { k1.x, k1.y }, b3[2] = { k1.z, k1.w };
                hmma16h(c0, qa[0][0], b0); hmma16h(c0, qa[0][1], b1);
                hmma16h(c0, qa[0][2], b2); hmma16h(c0, qa[0][3], b3);
                hmma16h(c1, qa[1][0], b0); hmma16h(c1, qa[1][1], b1);
                hmma16h(c1, qa[1][2], b2); hmma16h(c1, qa[1][3], b3);

                if (diag) {
                    const int cc = jb * 64 + n * 8 + 2 * q;
                    const int rL = r0 + g, rH = rL + 8;
                    unsigned m;
                    m = (cc > rL ? NINF_LO : 0u) | (cc + 1 > rL ? NINF_HI : 0u);
                    if (m) c0[0] = hadd2(c0[0], m);
                    m = (cc > rH ? NINF_LO : 0u) | (cc + 1 > rH ? NINF_HI : 0u);
                    if (m) c0[1] = hadd2(c0[1], m);
                    m = (cc > rL + 16 ? NINF_LO : 0u) | (cc + 1 > rL + 16 ? NINF_HI : 0u);
                    if (m) c1[0] = hadd2(c1[0], m);
                    m = (cc > rH + 16 ? NINF_LO : 0u) | (cc + 1 > rH + 16 ? NINF_HI : 0u);
                    if (m) c1[1] = hadd2(c1[1], m);
                }

                pp[0][n][0] = hex2(c0[0]); pp[0][n][1] = hex2(c0[1]);
                pp[1][n][0] = hex2(c1[0]); pp[1][n][1] = hex2(c1[1]);
            }

            // ---- acc += P @ V ; l += P @ 1  (pp ARE the A-frags)
            #pragma unroll
            for (int t = 0; t < 4; t++) {
                unsigned pa[2][4];
                #pragma unroll
                for (int mi = 0; mi < 2; mi++) {
                    pa[mi][0] = pp[mi][2 * t][0];
                    pa[mi][1] = pp[mi][2 * t][1];
                    pa[mi][2] = pp[mi][2 * t + 1][0];
                    pa[mi][3] = pp[mi][2 * t + 1][1];
                }
                hmma16(accl[0], pa[0], ONES);
                hmma16(accl[1], pa[1], ONES);
                #pragma unroll
                for (int n = 0; n < 8; n++) {
                    unsigned vb[2] = {
                        *(const unsigned*)&V[(t * 8 + q) * VST + n * 8 + g],
                        *(const unsigned*)&V[(t * 8 + q + 4) * VST + n * 8 + g] };
                    hmma16(acc[0][n], pa[0], vb);
                    hmma16(acc[1][n], pa[1], vb);
                }
            }
        }
    }

    #pragma unroll
    for (int mi = 0; mi < 2; mi++) {
        const float inv0 = 1.f / accl[mi][0], inv1 = 1.f / accl[mi][2];
        const size_t tokL = (size_t)(b * S_LEN + r0 + mi * 16 + g);
        const size_t tokH = tokL + 8;
        #pragma unroll
        for (int n = 0; n < 8; n++) {
            const int c = h * 64 + n * 8 + 2 * q;
            *(unsigned*)&outh[tokL * HDIM + c] = pkh2(acc[mi][n][1] * inv0, acc[mi][n][0] * inv0);
            *(unsigned*)&outh[tokH * HDIM + c] = pkh2(acc[mi][n][3] * inv1, acc[mi][n][2] * inv1);
        }
    }
}

// ---------------------------------------------------------------------------
// Launch
// ---------------------------------------------------------------------------
extern "C" void kernel_launch(void* const* d_in, const int* in_sizes, int n_in,
                              void* d_out, int out_size) {
    const float* x     = (const float*)d_in[0];
    const float* w_qkv = (const float*)d_in[1];
    const float* w_o   = (const float*)d_in[2];
    float* out = (float*)d_out;

    float* qkv; __half *xh, *wqh, *woh, *ath, *khp, *vph;
    cudaGetSymbolAddress((void**)&qkv, g_qkv);
    cudaGetSymbolAddress((void**)&xh,  g_xh);
    cudaGetSymbolAddress((void**)&wqh, g_wqh);
    cudaGetSymbolAddress((void**)&woh, g_woh);
    cudaGetSymbolAddress((void**)&ath, g_ath);
    cudaGetSymbolAddress((void**)&khp, g_kh);
    cudaGetSymbolAddress((void**)&vph, g_vph);

    // 0) fp16 conversions
    cvt_h<<<(TOKENS * HDIM / 4 + 255) / 256, 256>>>(x, xh, TOKENS * HDIM / 4);
    cvt_h<<<(3 * HDIM * HDIM / 4 + 255) / 256, 256>>>(w_qkv, wqh, 3 * HDIM * HDIM / 4);
    cvt_h<<<(HDIM * HDIM / 4 + 255) / 256, 256>>>(w_o, woh, HDIM * HDIM / 4);

    // 1) QKV projection
    cudaFuncSetAttribute(gemm_h_nt, cudaFuncAttributeMaxDynamicSharedMemorySize, GSM);
    gemm_h_nt<<<dim3(3 * HDIM / 128, TOKENS / 128), 256, GSM>>>(xh, wqh, qkv, TOKENS, 3 * HDIM, HDIM);

    // 2) RoPE + K fp16 frag-reorder + V fp16 pairing
    rope_kernel<<<(TOKENS * NH * 32) / 256, 256>>>(qkv, khp, vph);

    // 3) Causal flash attention (f16-accum QK, 3 CTAs/SM) -> att fp16
    const int flash_smem = 2 * 64 * KH * 2 + 2 * 32 * VST * 4;  // 36864 B
    cudaFuncSetAttribute(flash2, cudaFuncAttributeMaxDynamicSharedMemorySize, flash_smem);
    flash2<<<dim3(S_LEN / 128, 2 * NH), 128, flash_smem>>>(qkv, khp, (const __half2*)vph, ath);

    // 4) Output projection
    gemm_h_nt<<<dim3(HDIM / 128, TOKENS / 128), 256, GSM>>>(ath, woh, out, TOKENS, HDIM, HDIM);
}

// round 17
// speedup vs baseline: 1.1031x; 1.0895x over previous
#include <cuda_runtime.h>
#include <cuda_fp16.h>
#include <math.h>

#define TOKENS 4096      // B*S = 2*2048
#define S_LEN  2048
#define HDIM   1024
#define NH     16

// Scratch (static device globals — no allocations allowed)
__device__ __align__(256) __half g_xh [(size_t)TOKENS * HDIM];     // x in fp16
__device__ __align__(256) __half g_wqh[(size_t)3 * HDIM * HDIM];   // w_qkv fp16
__device__ __align__(256) __half g_woh[(size_t)HDIM * HDIM];       // w_o fp16
__device__ __align__(256) __half g_qh [(size_t)TOKENS * HDIM];     // q fp16 (roped, pre-scaled)
__device__ __align__(256) __half g_ath[(size_t)TOKENS * HDIM];     // att fp16
__device__ __align__(256) __half g_kh [(size_t)32 * S_LEN * 64];   // K fp16 frag-ordered
__device__ __align__(256) __half g_vph[(size_t)32 * 1024 * 64 * 2]; // V half2 pairs
__device__ __align__(256) float2 g_rope[(size_t)S_LEN * 32];       // (cos,sin) per (s, i)

// ---------------------------------------------------------------------------
// Helpers
// ---------------------------------------------------------------------------
__device__ __forceinline__ void hmma16(float* c, const unsigned* a, const unsigned* b) {
    asm("mma.sync.aligned.m16n8k16.row.col.f32.f16.f16.f32 "
        "{%0,%1,%2,%3}, {%4,%5,%6,%7}, {%8,%9}, {%0,%1,%2,%3};"
        : "+f"(c[0]), "+f"(c[1]), "+f"(c[2]), "+f"(c[3])
        : "r"(a[0]), "r"(a[1]), "r"(a[2]), "r"(a[3]), "r"(b[0]), "r"(b[1]));
}
// f16-accumulate variant: C/D are 2 regs of f16x2 ({col 2q, col 2q+1} packed)
__device__ __forceinline__ void hmma16h(unsigned* c, const unsigned* a, const unsigned* b) {
    asm("mma.sync.aligned.m16n8k16.row.col.f16.f16.f16.f16 "
        "{%0,%1}, {%2,%3,%4,%5}, {%6,%7}, {%0,%1};"
        : "+r"(c[0]), "+r"(c[1])
        : "r"(a[0]), "r"(a[1]), "r"(a[2]), "r"(a[3]), "r"(b[0]), "r"(b[1]));
}
__device__ __forceinline__ unsigned pkh2(float hi, float lo) {
    unsigned d; asm("cvt.rn.f16x2.f32 %0, %1, %2;" : "=r"(d) : "f"(hi), "f"(lo)); return d;
}
__device__ __forceinline__ unsigned hex2(unsigned x) {
    unsigned y; asm("ex2.approx.f16x2 %0, %1;" : "=r"(y) : "r"(x)); return y;
}
__device__ __forceinline__ unsigned hadd2(unsigned a, unsigned b) {
    unsigned d; asm("add.rn.f16x2 %0, %1, %2;" : "=r"(d) : "r"(a), "r"(b)); return d;
}
__device__ __forceinline__ void cpa16(void* s, const void* g) {
    unsigned sa = (unsigned)__cvta_generic_to_shared(s);
    asm volatile("cp.async.cg.shared.global [%0], [%1], 16;" :: "r"(sa), "l"(g));
}
__device__ __forceinline__ void cp_commit() { asm volatile("cp.async.commit_group;"); }
__device__ __forceinline__ void cp_wait0()  { asm volatile("cp.async.wait_group 0;"); }
__device__ __forceinline__ void cp_wait1()  { asm volatile("cp.async.wait_group 1;"); }
__device__ __forceinline__ void ldmx4(unsigned* r, unsigned addr) {
    asm volatile("ldmatrix.sync.aligned.m8n8.x4.shared.b16 {%0,%1,%2,%3}, [%4];"
        : "=r"(r[0]), "=r"(r[1]), "=r"(r[2]), "=r"(r[3]) : "r"(addr));
}

// ---------------------------------------------------------------------------
// Setup: fp32->fp16 conversions (x, w_qkv, w_o) + RoPE cos/sin table.
// Table math matches the old rope kernel exactly (double exp, cosf/sinf).
// ---------------------------------------------------------------------------
#define NC1 (TOKENS * HDIM / 4)
#define NC2 (3 * HDIM * HDIM / 4)
#define NC3 (HDIM * HDIM / 4)
#define NTAB (S_LEN * 32)
#define NSETUP (NC1 + NC2 + NC3 + NTAB)
__global__ void setup_k(const float* __restrict__ x, const float* __restrict__ wq,
                        const float* __restrict__ wo, __half* __restrict__ xh,
                        __half* __restrict__ wqh, __half* __restrict__ woh,
                        float2* __restrict__ tab) {
    int i = blockIdx.x * blockDim.x + threadIdx.x;
    const float* s; __half* d; int j;
    if (i < NC1)             { s = x;  d = xh;  j = i; }
    else if (i < NC1 + NC2)  { s = wq; d = wqh; j = i - NC1; }
    else if (i < NC1 + NC2 + NC3) { s = wo; d = woh; j = i - NC1 - NC2; }
    else if (i < NSETUP) {
        int t  = i - (NC1 + NC2 + NC3);
        int ss = t >> 5, ii = t & 31;
        float invf = (float)exp(-((double)ii / 32.0) * log(10000.0));
        float ang  = (float)ss * invf;
        tab[t] = make_float2(cosf(ang), sinf(ang));
        return;
    } else return;
    float4 v = ((const float4*)s)[j];
    ((uint2*)d)[j] = make_uint2(pkh2(v.y, v.x), pkh2(v.w, v.z));
}

// ---------------------------------------------------------------------------
// QKV GEMM with fused RoPE epilogue. Mainloop identical to gemm_h_nt
// (128x128 tile, 256 thr, warp 32x64, 3-stage cp.async). N=3072, K=1024.
// Epilogue: cols d and d+32 live in the same thread (ni, ni+4) -> rotate in
// registers using g_rope, then write q (fp16, SC-scaled), k (frag order),
// v (paired half2) directly. No fp32 qkv tensor, no rope kernel.
// ---------------------------------------------------------------------------
#define GSM (3 * 32768)
__global__ void __launch_bounds__(256, 2) gemm_qkv(
        const __half* __restrict__ A, const __half* __restrict__ B,
        __half* __restrict__ qh, __half* __restrict__ kh,
        __half* __restrict__ vph, const float2* __restrict__ tab) {
    extern __shared__ char smx[];
    const int K = HDIM;
    const int tid = threadIdx.x, lane = tid & 31;
    const int w   = tid >> 5, wm = w >> 1, wn = w & 1;
    const int g   = lane >> 2, q = lane & 3;

    const int lr = tid >> 3, lc = tid & 7;
    const __half* Ab = A + (size_t)(blockIdx.y * 128) * K + lc * 8;
    const __half* Bb = B + (size_t)(blockIdx.x * 128) * K + lc * 8;
    const unsigned sbase = (unsigned)__cvta_generic_to_shared(smx);

    const int lrow = ((lane >> 3) & 1) * 8 + (lane & 7);
    const unsigned rbA = sbase + (unsigned)(wm * 32 + lrow) * 128;
    const unsigned rbB = sbase + 16384u + (unsigned)(wn * 64 + lrow) * 128;
    const int gsel = lane >> 4;
    const int r7   = lane & 7;

    float acc[2][8][4] = {};
    const int nS = K >> 6;

    #pragma unroll
    for (int st = 0; st < 2; st++) {
        char* As = smx + st * 32768;
        char* Bs = As + 16384;
        const __half* a = Ab + st * 64;
        const __half* b = Bb + st * 64;
        #pragma unroll
        for (int i = 0; i < 4; i++) {
            const int r = lr + i * 32;
            const unsigned doff = (unsigned)(r * 128 + ((lc ^ (r & 7)) * 16));
            cpa16(As + doff, a + (size_t)r * K);
            cpa16(Bs + doff, b + (size_t)r * K);
        }
        cp_commit();
    }

    for (int s = 0; s < nS; s++) {
        cp_wait1();
        __syncthreads();

        if (s + 2 < nS) {
            char* As = smx + ((s + 2) % 3) * 32768;
            char* Bs = As + 16384;
            const __half* a = Ab + (s + 2) * 64;
            const __half* b = Bb + (s + 2) * 64;
            #pragma unroll
            for (int i = 0; i < 4; i++) {
                const int r = lr + i * 32;
                const unsigned doff = (unsigned)(r * 128 + ((lc ^ (r & 7)) * 16));
                cpa16(As + doff, a + (size_t)r * K);
                cpa16(Bs + doff, b + (size_t)r * K);
            }
        }
        cp_commit();

        const unsigned so = (unsigned)((s % 3) * 32768);
        #pragma unroll
        for (int kgi = 0; kgi < 4; kgi++) {
            const unsigned xo = (unsigned)((((kgi << 1) | gsel) ^ r7) * 16);
            unsigned af[2][4], bf[4][4];
            #pragma unroll
            for (int mb = 0; mb < 2; mb++) ldmx4(af[mb], rbA + so + mb * 2048 + xo);
            #pragma unroll
            for (int np = 0; np < 4; np++) ldmx4(bf[np], rbB + so + np * 2048 + xo);
            #pragma unroll
            for (int mb = 0; mb < 2; mb++)
                #pragma unroll
                for (int ni = 0; ni < 8; ni++) {
                    unsigned bb[2] = { bf[ni >> 1][ni & 1], bf[ni >> 1][(ni & 1) + 2] };
                    hmma16(acc[mb][ni], af[mb], bb);
                }
        }
        __syncthreads();
    }

    // ---- fused epilogue --------------------------------------------------
    const int region = blockIdx.x >> 3;                 // 0=q, 1=k, 2=v
    const int colr   = (blockIdx.x & 7) * 128 + wn * 64; // col in region
    const int h      = colr >> 6;
    const int tok0   = blockIdx.y * 128 + wm * 32;
    const float SC   = 0.125f * 1.44269504088896340736f;

    if (region == 2) {
        // V: no rope; scatter paired half2 layout
        #pragma unroll
        for (int mb = 0; mb < 2; mb++) {
            #pragma unroll
            for (int rr = 0; rr < 2; rr++) {
                const int tok = tok0 + mb * 16 + g + rr * 8;
                const int s   = tok & (S_LEN - 1);
                const int bhv = ((tok >> 11) << 4) + h;
                __half* vb = vph + (((size_t)bhv * 1024 + (s >> 1)) * 64) * 2 + (s & 1);
                #pragma unroll
                for (int ni = 0; ni < 8; ni++) {
                    const int d = ni * 8 + 2 * q;
                    vb[2 * d]       = __float2half_rn(acc[mb][ni][rr * 2 + 0]);
                    vb[2 * (d + 1)] = __float2half_rn(acc[mb][ni][rr * 2 + 1]);
                }
            }
        }
    } else {
        // Q / K: rotate (d, d+32) pairs in registers via rope table
        #pragma unroll
        for (int mb = 0; mb < 2; mb++) {
            #pragma unroll
            for (int rr = 0; rr < 2; rr++) {
                const int tok = tok0 + mb * 16 + g + rr * 8;
                const int s   = tok & (S_LEN - 1);
                #pragma unroll
                for (int ni = 0; ni < 4; ni++) {
                    const int d = ni * 8 + 2 * q;
                    const float4 t = *(const float4*)&tab[s * 32 + d]; // c0,s0,c1,s1
                    const float x0 = acc[mb][ni][rr * 2],     x1 = acc[mb][ni][rr * 2 + 1];
                    const float y0 = acc[mb][ni + 4][rr * 2], y1 = acc[mb][ni + 4][rr * 2 + 1];
                    const float a0 = x0 * t.x - y0 * t.y, b0 = y0 * t.x + x0 * t.y;
                    const float a1 = x1 * t.z - y1 * t.w, b1 = y1 * t.z + x1 * t.w;
                    if (region == 0) {
                        __half* qb = qh + (size_t)tok * HDIM + h * 64;
                        *(unsigned*)&qb[d]      = pkh2(a1 * SC, a0 * SC);
                        *(unsigned*)&qb[d + 32] = pkh2(b1 * SC, b0 * SC);
                    } else {
                        __half* kb = kh + ((size_t)(((tok >> 11) << 4) + h) * S_LEN + s) * 64;
                        const int pos = ((d & 7) >> 1) * 16 + (d >> 4) * 4 + ((d >> 3) & 1) * 2;
                        *(unsigned*)&kb[pos]     = pkh2(a1, a0);
                        *(unsigned*)&kb[pos + 8] = pkh2(b1, b0);
                    }
                }
            }
        }
    }
}

// ---------------------------------------------------------------------------
// Generic fp16 GEMM (O-projection): C[M,N] = A[M,K] @ B[N,K]^T, f32 out.
// ---------------------------------------------------------------------------
__global__ void __launch_bounds__(256, 2) gemm_h_nt(
        const __half* __restrict__ A, const __half* __restrict__ B,
        float* __restrict__ C, int M, int N, int K) {
    extern __shared__ char smx[];
    const int tid = threadIdx.x, lane = tid & 31;
    const int w   = tid >> 5, wm = w >> 1, wn = w & 1;
    const int g   = lane >> 2, q = lane & 3;

    const int lr = tid >> 3, lc = tid & 7;
    const __half* Ab = A + (size_t)(blockIdx.y * 128) * K + lc * 8;
    const __half* Bb = B + (size_t)(blockIdx.x * 128) * K + lc * 8;
    const unsigned sbase = (unsigned)__cvta_generic_to_shared(smx);

    const int lrow = ((lane >> 3) & 1) * 8 + (lane & 7);
    const unsigned rbA = sbase + (unsigned)(wm * 32 + lrow) * 128;
    const unsigned rbB = sbase + 16384u + (unsigned)(wn * 64 + lrow) * 128;
    const int gsel = lane >> 4;
    const int r7   = lane & 7;

    float acc[2][8][4] = {};
    const int nS = K >> 6;

    #pragma unroll
    for (int st = 0; st < 2; st++) {
        char* As = smx + st * 32768;
        char* Bs = As + 16384;
        const __half* a = Ab + st * 64;
        const __half* b = Bb + st * 64;
        #pragma unroll
        for (int i = 0; i < 4; i++) {
            const int r = lr + i * 32;
            const unsigned doff = (unsigned)(r * 128 + ((lc ^ (r & 7)) * 16));
            cpa16(As + doff, a + (size_t)r * K);
            cpa16(Bs + doff, b + (size_t)r * K);
        }
        cp_commit();
    }

    for (int s = 0; s < nS; s++) {
        cp_wait1();
        __syncthreads();

        if (s + 2 < nS) {
            char* As = smx + ((s + 2) % 3) * 32768;
            char* Bs = As + 16384;
            const __half* a = Ab + (s + 2) * 64;
            const __half* b = Bb + (s + 2) * 64;
            #pragma unroll
            for (int i = 0; i < 4; i++) {
                const int r = lr + i * 32;
                const unsigned doff = (unsigned)(r * 128 + ((lc ^ (r & 7)) * 16));
                cpa16(As + doff, a + (size_t)r * K);
                cpa16(Bs + doff, b + (size_t)r * K);
            }
        }
        cp_commit();

        const unsigned so = (unsigned)((s % 3) * 32768);
        #pragma unroll
        for (int kgi = 0; kgi < 4; kgi++) {
            const unsigned xo = (unsigned)((((kgi << 1) | gsel) ^ r7) * 16);
            unsigned af[2][4], bf[4][4];
            #pragma unroll
            for (int mb = 0; mb < 2; mb++) ldmx4(af[mb], rbA + so + mb * 2048 + xo);
            #pragma unroll
            for (int np = 0; np < 4; np++) ldmx4(bf[np], rbB + so + np * 2048 + xo);
            #pragma unroll
            for (int mb = 0; mb < 2; mb++)
                #pragma unroll
                for (int ni = 0; ni < 8; ni++) {
                    unsigned bb[2] = { bf[ni >> 1][ni & 1], bf[ni >> 1][(ni & 1) + 2] };
                    hmma16(acc[mb][ni], af[mb], bb);
                }
        }
        __syncthreads();
    }

    #pragma unroll
    for (int mb = 0; mb < 2; mb++) {
        const int row = blockIdx.y * 128 + wm * 32 + mb * 16 + g;
        #pragma unroll
        for (int ni = 0; ni < 8; ni++) {
            const int col = blockIdx.x * 128 + wn * 64 + ni * 8 + 2 * q;
            *(float2*)&C[(size_t)row * N + col]       = make_float2(acc[mb][ni][0], acc[mb][ni][1]);
            *(float2*)&C[(size_t)(row + 8) * N + col] = make_float2(acc[mb][ni][2], acc[mb][ni][3]);
        }
    }
}

// ---------------------------------------------------------------------------
// Flash attention: f16-accum QK (S emerges pre-packed f16x2 -> ex2 direct),
// causal mask via add.rn.f16x2(-inf), PV + ones-MMA row-sum in f32.
// Q read directly as fp16 (pre-scaled by gemm_qkv). 3 CTAs/SM.
// ---------------------------------------------------------------------------
#define KH  72
#define VST 72
#define NINF_LO 0x0000FC00u
#define NINF_HI 0xFC000000u
__global__ void __launch_bounds__(128, 3) flash2(const __half* __restrict__ qh,
                                                 const __half* __restrict__ kh,
                                                 const __half2* __restrict__ vp,
                                                 __half* __restrict__ outh) {
    extern __shared__ float sm[];
    __half*  KsB = (__half*)sm;                         // [2][64][KH]
    __half2* VsB = (__half2*)(sm + (2 * 64 * KH) / 2);  // [2][32][VST]

    const int tid = threadIdx.x, lane = tid & 31, w = tid >> 5;
    const int g   = lane >> 2, q = lane & 3;
    const int qb  = gridDim.x - 1 - blockIdx.x;
    const int bh  = blockIdx.y;
    const int b   = bh >> 4, h = bh & 15;
    const int r0  = qb * 128 + w * 32;

    // ---- Q fp16 A-fragments: direct 32-bit loads (pre-scaled, pre-roped)
    unsigned qa[2][4][4];
    #pragma unroll
    for (int mi = 0; mi < 2; mi++) {
        const __half* ql = qh + (size_t)(b * S_LEN + r0 + mi * 16 + g) * HDIM + h * 64;
        const __half* qh8 = ql + (size_t)8 * HDIM;
        #pragma unroll
        for (int kg = 0; kg < 4; kg++) {
            qa[mi][kg][0] = *(const unsigned*)(ql  + kg * 16 + 2 * q);
            qa[mi][kg][1] = *(const unsigned*)(qh8 + kg * 16 + 2 * q);
            qa[mi][kg][2] = *(const unsigned*)(ql  + kg * 16 + 8 + 2 * q);
            qa[mi][kg][3] = *(const unsigned*)(qh8 + kg * 16 + 8 + 2 * q);
        }
    }

    float acc[2][8][4] = {};
    float accl[2][4] = {};
    const unsigned ONES[2] = { 0x3C003C00u, 0x3C003C00u };

    const __half*  Kpl = kh + (size_t)bh * S_LEN * 64;
    const __half2* Vpl = vp + (size_t)bh * 1024 * 64;

    const int kR = tid >> 3, kC = (tid & 7) * 8;
    const int vR = tid >> 2, vC = (tid & 3) * 16;
    const int jmax = 2 * qb + 1;

    {
        #pragma unroll
        for (int i = 0; i < 4; i++)
            cpa16(KsB + (kR + i * 16) * KH + kC, Kpl + (size_t)(kR + i * 16) * 64 + kC);
        #pragma unroll
        for (int i = 0; i < 4; i++)
            cpa16(VsB + vR * VST + vC + 4 * i, Vpl + (size_t)vR * 64 + vC + 4 * i);
    }
    cp_commit();

    for (int jb = 0; jb <= jmax; jb++) {
        cp_wait0();
        __syncthreads();

        if (jb < jmax) {
            const int nb = (jb + 1) & 1;
            const __half*  ks = Kpl + (size_t)((jb + 1) * 64) * 64;
            const __half2* vs = Vpl + (size_t)((jb + 1) * 32 + vR) * 64 + vC;
            #pragma unroll
            for (int i = 0; i < 4; i++)
                cpa16(KsB + (nb * 64 + kR + i * 16) * KH + kC, ks + (size_t)(kR + i * 16) * 64 + kC);
            #pragma unroll
            for (int i = 0; i < 4; i++)
                cpa16(VsB + (nb * 32 + vR) * VST + vC + 4 * i, vs + 4 * i);
            cp_commit();
        }

        if (r0 + 31 >= jb * 64) {
            const __half*  K = KsB + (jb & 1) * 64 * KH;
            const __half2* V = VsB + (jb & 1) * 32 * VST;
            const bool diag = (jb * 64 + 63 > r0);

            // ---- S = Q @ K^T in f16 accum; mask; p = 2^s (packed MUFU)
            unsigned pp[2][8][2];
            #pragma unroll
            for (int n = 0; n < 8; n++) {
                unsigned c0[2] = { 0u, 0u }, c1[2] = { 0u, 0u };
                const uint4* krow = (const uint4*)(K + (n * 8 + g) * KH + q * 16);
                uint4 k0 = krow[0];
                uint4 k1 = krow[1];
                unsigned b0[2] = { k0.x, k0.y }, b1[2] = { k0.z, k0.w };
                unsigned b2[2] = { k1.x, k1.y }, b3[2] = { k1.z, k1.w };
                hmma16h(c0, qa[0][0], b0); hmma16h(c0, qa[0][1], b1);
                hmma16h(c0, qa[0][2], b2); hmma16h(c0, qa[0][3], b3);
                hmma16h(c1, qa[1][0], b0); hmma16h(c1, qa[1][1], b1);
                hmma16h(c1, qa[1][2], b2); hmma16h(c1, qa[1][3], b3);

                if (diag) {
                    const int cc = jb * 64 + n * 8 + 2 * q;
                    const int rL = r0 + g, rH = rL + 8;
                    unsigned m;
                    m = (cc > rL ? NINF_LO : 0u) | (cc + 1 > rL ? NINF_HI : 0u);
                    if (m) c0[0] = hadd2(c0[0], m);
                    m = (cc > rH ? NINF_LO : 0u) | (cc + 1 > rH ? NINF_HI : 0u);
                    if (m) c0[1] = hadd2(c0[1], m);
                    m = (cc > rL + 16 ? NINF_LO : 0u) | (cc + 1 > rL + 16 ? NINF_HI : 0u);
                    if (m) c1[0] = hadd2(c1[0], m);
                    m = (cc > rH + 16 ? NINF_LO : 0u) | (cc + 1 > rH + 16 ? NINF_HI : 0u);
                    if (m) c1[1] = hadd2(c1[1], m);
                }

                pp[0][n][0] = hex2(c0[0]); pp[0][n][1] = hex2(c0[1]);
                pp[1][n][0] = hex2(c1[0]); pp[1][n][1] = hex2(c1[1]);
            }

            // ---- acc += P @ V ; l += P @ 1  (pp ARE the A-frags)
            #pragma unroll
            for (int t = 0; t < 4; t++) {
                unsigned pa[2][4];
                #pragma unroll
                for (int mi = 0; mi < 2; mi++) {
                    pa[mi][0] = pp[mi][2 * t][0];
                    pa[mi][1] = pp[mi][2 * t][1];
                    pa[mi][2] = pp[mi][2 * t + 1][0];
                    pa[mi][3] = pp[mi][2 * t + 1][1];
                }
                hmma16(accl[0], pa[0], ONES);
                hmma16(accl[1], pa[1], ONES);
                #pragma unroll
                for (int n = 0; n < 8; n++) {
                    unsigned vb[2] = {
                        *(const unsigned*)&V[(t * 8 + q) * VST + n * 8 + g],
                        *(const unsigned*)&V[(t * 8 + q + 4) * VST + n * 8 + g] };
                    hmma16(acc[0][n], pa[0], vb);
                    hmma16(acc[1][n], pa[1], vb);
                }
            }
        }
    }

    #pragma unroll
    for (int mi = 0; mi < 2; mi++) {
        const float inv0 = 1.f / accl[mi][0], inv1 = 1.f / accl[mi][2];
        const size_t tokL = (size_t)(b * S_LEN + r0 + mi * 16 + g);
        const size_t tokH = tokL + 8;
        #pragma unroll
        for (int n = 0; n < 8; n++) {
            const int c = h * 64 + n * 8 + 2 * q;
            *(unsigned*)&outh[tokL * HDIM + c] = pkh2(acc[mi][n][1] * inv0, acc[mi][n][0] * inv0);
            *(unsigned*)&outh[tokH * HDIM + c] = pkh2(acc[mi][n][3] * inv1, acc[mi][n][2] * inv1);
        }
    }
}

// ---------------------------------------------------------------------------
// Launch
// ---------------------------------------------------------------------------
extern "C" void kernel_launch(void* const* d_in, const int* in_sizes, int n_in,
                              void* d_out, int out_size) {
    const float* x     = (const float*)d_in[0];
    const float* w_qkv = (const float*)d_in[1];
    const float* w_o   = (const float*)d_in[2];
    float* out = (float*)d_out;

    __half *xh, *wqh, *woh, *qhp, *ath, *khp, *vph; float2* tab;
    cudaGetSymbolAddress((void**)&xh,  g_xh);
    cudaGetSymbolAddress((void**)&wqh, g_wqh);
    cudaGetSymbolAddress((void**)&woh, g_woh);
    cudaGetSymbolAddress((void**)&qhp, g_qh);
    cudaGetSymbolAddress((void**)&ath, g_ath);
    cudaGetSymbolAddress((void**)&khp, g_kh);
    cudaGetSymbolAddress((void**)&vph, g_vph);
    cudaGetSymbolAddress((void**)&tab, g_rope);

    // 0) fp16 conversions + rope table (single launch)
    setup_k<<<(NSETUP + 255) / 256, 256>>>(x, w_qkv, w_o, xh, wqh, woh, tab);

    // 1) QKV projection with fused RoPE epilogue -> q/k/v fp16 layouts
    cudaFuncSetAttribute(gemm_qkv, cudaFuncAttributeMaxDynamicSharedMemorySize, GSM);
    gemm_qkv<<<dim3(3 * HDIM / 128, TOKENS / 128), 256, GSM>>>(xh, wqh, qhp, khp, vph, tab);

    // 2) Causal flash attention -> att fp16
    const int flash_smem = 2 * 64 * KH * 2 + 2 * 32 * VST * 4;  // 36864 B
    cudaFuncSetAttribute(flash2, cudaFuncAttributeMaxDynamicSharedMemorySize, flash_smem);
    flash2<<<dim3(S_LEN / 128, 2 * NH), 128, flash_smem>>>(qhp, khp, (const __half2*)vph, ath);

    // 3) Output projection
    cudaFuncSetAttribute(gemm_h_nt, cudaFuncAttributeMaxDynamicSharedMemorySize, GSM);
    gemm_h_nt<<<dim3(HDIM / 128, TOKENS / 128), 256, GSM>>>(ath, woh, out, TOKENS, HDIM, HDIM);
}